// round 12
// baseline (speedup 1.0000x reference)
#include <cuda_runtime.h>
#include <cuda_bf16.h>
#include <cstdint>
#include <cstddef>

#define Nn 50000
#define Ee 250000
#define Ll 4

// bf16 tile layout: [rows][136 cols] bf16 (row pad 8 -> 272B stride, conflict-free)
// M-tile = 128 rows. A: 128x272 x2 (hi/lo). B: single 128x272 buffer (hi OR lo phase).
#define ROWB 272
#define OFF_AHI 0u
#define OFF_ALO 34816u
#define OFF_B   69632u
#define OFF_RED 104448u            // sSum[2][128], sSq[2][128]
#define SMEM_TOTAL (104448 + 2048)

// ---------------- global scratch (static, allocation-free) ----------------
__device__ float g_PQ[(size_t)Nn * 256];                 // [N][256]: P | Q
__device__ float g_agg[(size_t)Nn * 128];                // scatter accumulator
__device__ __align__(16) unsigned char g_Wb[28 * 69632]; // prepped weights (hi + lo tiles)

// ---------------------------------------------------------------------------
__device__ __forceinline__ uint32_t smem_u32(const void* p) {
    uint32_t a;
    asm("{ .reg .u64 t; cvta.to.shared.u64 t, %1; cvt.u32.u64 %0, t; }" : "=r"(a) : "l"(p));
    return a;
}

__device__ __forceinline__ void split2(float x, float y, uint32_t& hi, uint32_t& lo) {
    __nv_bfloat162 h = __floats2bfloat162_rn(x, y);
    float2 hf = __bfloat1622float2(h);
    __nv_bfloat162 l = __floats2bfloat162_rn(x - hf.x, y - hf.y);
    hi = *reinterpret_cast<uint32_t*>(&h);
    lo = *reinterpret_cast<uint32_t*>(&l);
}

__device__ __forceinline__ void mma_bf16(float* d, uint32_t a0, uint32_t a1, uint32_t a2,
                                         uint32_t a3, uint32_t b0, uint32_t b1) {
    asm volatile(
        "mma.sync.aligned.m16n8k16.row.col.f32.bf16.bf16.f32 "
        "{%0,%1,%2,%3}, {%4,%5,%6,%7}, {%8,%9}, {%0,%1,%2,%3};"
        : "+f"(d[0]), "+f"(d[1]), "+f"(d[2]), "+f"(d[3])
        : "r"(a0), "r"(a1), "r"(a2), "r"(a3), "r"(b0), "r"(b1));
}

// 128x128x128 GEMM pass over the single B buffer. Warp tile 32m x 64n (8 warps).
// TWO_TERM=1: acc += Ahi*B + Alo*B (B holds W-hi)
// TWO_TERM=0: acc += Ahi*B          (B holds W-lo)
template <int TWO_TERM>
__device__ __forceinline__ void gemm_pass(const char* sm, float (&acc)[2][8][4],
                                          int mrow0, int ncol0, int g, int tg) {
    const char* Ah = sm + OFF_AHI;
    const char* Al = sm + OFF_ALO;
    const char* Bp = sm + OFF_B;
#pragma unroll
    for (int ks = 0; ks < 8; ++ks) {
        int kb = ks * 32 + tg * 4;
        uint32_t aH[2][4], aL[2][4];
#pragma unroll
        for (int mt = 0; mt < 2; ++mt) {
            int r = mrow0 + 16 * mt + g;
            const char* p0 = Ah + r * ROWB + kb;
            const char* p1 = Ah + (r + 8) * ROWB + kb;
            aH[mt][0] = *(const uint32_t*)(p0);
            aH[mt][1] = *(const uint32_t*)(p1);
            aH[mt][2] = *(const uint32_t*)(p0 + 16);
            aH[mt][3] = *(const uint32_t*)(p1 + 16);
            if (TWO_TERM) {
                const char* q0 = Al + r * ROWB + kb;
                const char* q1 = Al + (r + 8) * ROWB + kb;
                aL[mt][0] = *(const uint32_t*)(q0);
                aL[mt][1] = *(const uint32_t*)(q1);
                aL[mt][2] = *(const uint32_t*)(q0 + 16);
                aL[mt][3] = *(const uint32_t*)(q1 + 16);
            }
        }
#pragma unroll
        for (int nh = 0; nh < 2; ++nh) {
            uint32_t bF[4][2];
#pragma unroll
            for (int ntl = 0; ntl < 4; ++ntl) {
                int n = ncol0 + 8 * (nh * 4 + ntl) + g;
                const char* p = Bp + n * ROWB + kb;
                bF[ntl][0] = *(const uint32_t*)(p);
                bF[ntl][1] = *(const uint32_t*)(p + 16);
            }
#pragma unroll
            for (int ntl = 0; ntl < 4; ++ntl)
#pragma unroll
                for (int mt = 0; mt < 2; ++mt) {
                    float* d = acc[mt][nh * 4 + ntl];
                    mma_bf16(d, aH[mt][0], aH[mt][1], aH[mt][2], aH[mt][3],
                             bF[ntl][0], bF[ntl][1]);
                    if (TWO_TERM)
                        mma_bf16(d, aL[mt][0], aL[mt][1], aL[mt][2], aL[mt][3],
                                 bF[ntl][0], bF[ntl][1]);
                }
        }
    }
}

// convert a [128 x 128] fp32 slab (rows clamped) into hi/lo padded bf16 tiles
__device__ __forceinline__ void conv_tile(char* sm, const float* __restrict__ src,
                                          int base, int maxrow, int tid) {
#pragma unroll
    for (int ii = 0; ii < 16; ++ii) {
        int i = tid + ii * 256;
        int row = i >> 5, c = (i & 31) * 4;
        int gr = base + row; if (gr > maxrow) gr = maxrow;
        float4 v = *(const float4*)(src + (size_t)gr * 128 + c);
        uint32_t h0, l0, h1, l1;
        split2(v.x, v.y, h0, l0);
        split2(v.z, v.w, h1, l1);
        int ob = row * ROWB + c * 2;
        *(uint2*)(sm + OFF_AHI + ob) = make_uint2(h0, h1);
        *(uint2*)(sm + OFF_ALO + ob) = make_uint2(l0, l1);
    }
}

// async copy one half (hi=0 / lo=1) of a prepped weight record (34816B) into B buffer
__device__ __forceinline__ void copy_B_half(uint32_t sb, int mat, int half, int tid) {
    const char* s = (const char*)(g_Wb + (size_t)mat * 69632 + (size_t)half * 34816);
    uint32_t d = sb + OFF_B;
#pragma unroll
    for (int ii = 0; ii < 9; ++ii) {
        int i = tid + ii * 256;
        if (i < 2176)
            asm volatile("cp.async.cg.shared.global [%0], [%1], 16;"
                         :: "r"(d + i * 16), "l"(s + (size_t)i * 16) : "memory");
    }
    asm volatile("cp.async.commit_group;" ::: "memory");
}
#define CP_WAIT0() asm volatile("cp.async.wait_group 0;" ::: "memory")

__device__ __forceinline__ void zero_acc(float (&acc)[2][8][4]) {
#pragma unroll
    for (int a = 0; a < 2; ++a)
#pragma unroll
        for (int b = 0; b < 8; ++b)
#pragma unroll
            for (int c = 0; c < 4; ++c) acc[a][b][c] = 0.f;
}

// ---------------------------------------------------------------------------
__global__ void zero_agg_kernel() {
    int i = blockIdx.x * blockDim.x + threadIdx.x;
    if (i < (Nn * 128) / 4) {
        float4 z = {0.f, 0.f, 0.f, 0.f};
        ((float4*)g_agg)[i] = z;
    }
}

// Pre-transpose + split into padded bf16 [n][k] layout. 28 matrices.
__global__ void prep_w(const float* __restrict__ eW1, const float* __restrict__ eW2,
                       const float* __restrict__ nW1, const float* __restrict__ nW2) {
    int m = blockIdx.x, l = m / 7, t = m % 7;
    const float* W;
    switch (t) {
        case 0: W = eW1 + (size_t)l * 3 * 16384;          break;
        case 1: W = eW1 + (size_t)l * 3 * 16384 + 16384;  break;
        case 2: W = eW1 + (size_t)l * 3 * 16384 + 32768;  break;
        case 3: W = eW2 + (size_t)l * 16384;              break;
        case 4: W = nW1 + (size_t)l * 2 * 16384;          break;
        case 5: W = nW1 + (size_t)l * 2 * 16384 + 16384;  break;
        default: W = nW2 + (size_t)l * 16384;             break;
    }
    size_t rec = (size_t)m * 69632;
    for (int i = threadIdx.x; i < 2048; i += 256) {
        int n = i >> 4, k8 = (i & 15) * 8;
        uint32_t hi[4], lo[4];
#pragma unroll
        for (int gi = 0; gi < 4; ++gi) {
            float a = W[(size_t)(k8 + 2 * gi) * 128 + n];
            float b = W[(size_t)(k8 + 2 * gi + 1) * 128 + n];
            split2(a, b, hi[gi], lo[gi]);
        }
        size_t ob = rec + (size_t)n * ROWB + k8 * 2;
        *(uint4*)(g_Wb + ob)         = make_uint4(hi[0], hi[1], hi[2], hi[3]);
        *(uint4*)(g_Wb + ob + 34816) = make_uint4(lo[0], lo[1], lo[2], lo[3]);
    }
}

// full 3-term GEMM via two passes over the single B buffer, with barriers.
__device__ __forceinline__ void gemm3(const char* sm, uint32_t sb, float (&acc)[2][8][4],
                                      int mat, int mrow0, int ncol0, int g, int tg, int tid) {
    gemm_pass<1>(sm, acc, mrow0, ncol0, g, tg);
    __syncthreads();                 // all warps done reading B-hi
    copy_B_half(sb, mat, 1, tid);    // swap in W-lo
    CP_WAIT0();
    __syncthreads();
    gemm_pass<0>(sm, acc, mrow0, ncol0, g, tg);
}

// ---------------------------------------------------------------------------
// PQ = x @ [W1a | W1b] -> g_PQ.  128 nodes/block.  (layer 0 only)
__global__ void __launch_bounds__(256, 2)
pq_kernel(const float* __restrict__ xb, int matA, int matB) {
    extern __shared__ char sm[];
    uint32_t sb = smem_u32(sm);
    int tid = threadIdx.x, w = tid >> 5, lane = tid & 31;
    int g = lane >> 2, tg = lane & 3;
    int base = blockIdx.x * 128;
    int mrow0 = (w >> 1) * 32, ncol0 = (w & 1) * 64;

    copy_B_half(sb, matA, 0, tid);
    conv_tile(sm, xb, base, Nn - 1, tid);
    CP_WAIT0();
    __syncthreads();

    float acc[2][8][4];
    zero_acc(acc);
    gemm3(sm, sb, acc, matA, mrow0, ncol0, g, tg, tid);
    __syncthreads();
    copy_B_half(sb, matB, 0, tid);   // W1b-hi fetch overlaps P writeback

#pragma unroll
    for (int mt = 0; mt < 2; ++mt)
#pragma unroll
        for (int p = 0; p < 2; ++p) {
            int n = base + mrow0 + 16 * mt + 8 * p + g;
            if (n < Nn) {
                float* dst = g_PQ + (size_t)n * 256;
#pragma unroll
                for (int nt = 0; nt < 8; ++nt) {
                    int col = ncol0 + 8 * nt + tg * 2;
                    *(float2*)(dst + col) = make_float2(acc[mt][nt][2 * p], acc[mt][nt][2 * p + 1]);
                }
            }
        }
    CP_WAIT0();
    __syncthreads();
    zero_acc(acc);
    gemm3(sm, sb, acc, matB, mrow0, ncol0, g, tg, tid);
#pragma unroll
    for (int mt = 0; mt < 2; ++mt)
#pragma unroll
        for (int p = 0; p < 2; ++p) {
            int n = base + mrow0 + 16 * mt + 8 * p + g;
            if (n < Nn) {
                float* dst = g_PQ + (size_t)n * 256 + 128;
#pragma unroll
                for (int nt = 0; nt < 8; ++nt) {
                    int col = ncol0 + 8 * nt + tg * 2;
                    *(float2*)(dst + col) = make_float2(acc[mt][nt][2 * p], acc[mt][nt][2 * p + 1]);
                }
            }
        }
}

// ---------------------------------------------------------------------------
// Fused edge kernel: 128 edges/block
__global__ void __launch_bounds__(256, 2)
edge_kernel(float* __restrict__ eab, const int* __restrict__ ei, int matW1c, int matW2,
            const float* __restrict__ b1, const float* __restrict__ b2,
            const float* __restrict__ gln, const float* __restrict__ bln) {
    extern __shared__ char sm[];
    uint32_t sb = smem_u32(sm);
    __shared__ int sI0[128], sI1[128];
    int tid = threadIdx.x, w = tid >> 5, lane = tid & 31;
    int g = lane >> 2, tg = lane & 3;
    int base = blockIdx.x * 128;
    int mrow0 = (w >> 1) * 32, ncol0 = (w & 1) * 64;
    int nhalf = w & 1;

    if (tid < 128) {
        int e = base + tid; if (e > Ee - 1) e = Ee - 1;
        sI0[tid] = ei[e];
        sI1[tid] = ei[Ee + e];
    }
    copy_B_half(sb, matW1c, 0, tid);
    conv_tile(sm, eab, base, Ee - 1, tid);
    CP_WAIT0();
    __syncthreads();

    float acc[2][8][4];
    zero_acc(acc);
    gemm3(sm, sb, acc, matW1c, mrow0, ncol0, g, tg, tid);   // ea @ W1c
    __syncthreads();                            // all A/B reads complete
    copy_B_half(sb, matW2, 0, tid);             // W2-hi fetch overlaps epi1 gathers

    // epi1: h = relu(D + P[i1] + Q[i0] + b1) -> back into A tiles (hi/lo)
    float2 b1v[8];
#pragma unroll
    for (int nt = 0; nt < 8; ++nt)
        b1v[nt] = *(const float2*)(b1 + ncol0 + 8 * nt + tg * 2);
#pragma unroll
    for (int mt = 0; mt < 2; ++mt)
#pragma unroll
        for (int p = 0; p < 2; ++p) {
            int r = mrow0 + 16 * mt + 8 * p + g;
            const float* Pp = g_PQ + (size_t)sI1[r] * 256;
            const float* Qp = g_PQ + (size_t)sI0[r] * 256 + 128;
#pragma unroll
            for (int nt = 0; nt < 8; ++nt) {
                int col = ncol0 + 8 * nt + tg * 2;
                float2 pv = *(const float2*)(Pp + col);
                float2 qv = *(const float2*)(Qp + col);
                float v0 = fmaxf(acc[mt][nt][2 * p]     + pv.x + qv.x + b1v[nt].x, 0.f);
                float v1 = fmaxf(acc[mt][nt][2 * p + 1] + pv.y + qv.y + b1v[nt].y, 0.f);
                uint32_t hi, lo;
                split2(v0, v1, hi, lo);
                int ob = r * ROWB + col * 2;
                *(uint32_t*)(sm + OFF_AHI + ob) = hi;
                *(uint32_t*)(sm + OFF_ALO + ob) = lo;
            }
        }
    CP_WAIT0();
    __syncthreads();

    zero_acc(acc);
    gemm3(sm, sb, acc, matW2, mrow0, ncol0, g, tg, tid);   // h @ W2

    // epi2: LN + residual + scatter
    float2 b2v[8], gv[8], bv[8];
#pragma unroll
    for (int nt = 0; nt < 8; ++nt) {
        int col = ncol0 + 8 * nt + tg * 2;
        b2v[nt] = *(const float2*)(b2 + col);
        gv[nt]  = *(const float2*)(gln + col);
        bv[nt]  = *(const float2*)(bln + col);
    }
    float* sSum = (float*)(sm + OFF_RED);
    float* sSq  = (float*)(sm + OFF_RED + 1024);
#pragma unroll
    for (int mt = 0; mt < 2; ++mt)
#pragma unroll
        for (int p = 0; p < 2; ++p) {
            float s = 0.f, q = 0.f;
#pragma unroll
            for (int nt = 0; nt < 8; ++nt) {
                float v0 = acc[mt][nt][2 * p]     + b2v[nt].x;
                float v1 = acc[mt][nt][2 * p + 1] + b2v[nt].y;
                s += v0 + v1; q += v0 * v0 + v1 * v1;
            }
            s += __shfl_xor_sync(0xffffffff, s, 1); q += __shfl_xor_sync(0xffffffff, q, 1);
            s += __shfl_xor_sync(0xffffffff, s, 2); q += __shfl_xor_sync(0xffffffff, q, 2);
            int r = mrow0 + 16 * mt + 8 * p + g;
            if (tg == 0) { sSum[nhalf * 128 + r] = s; sSq[nhalf * 128 + r] = q; }
        }
    __syncthreads();
#pragma unroll
    for (int mt = 0; mt < 2; ++mt)
#pragma unroll
        for (int p = 0; p < 2; ++p) {
            int r = mrow0 + 16 * mt + 8 * p + g;
            float mu = (sSum[r] + sSum[128 + r]) * (1.f / 128.f);
            float qq = (sSq[r]  + sSq[128 + r])  * (1.f / 128.f);
            float rs = rsqrtf(qq - mu * mu + 1e-5f);
            int e = base + r;
            if (e < Ee) {
                float* orow = eab + (size_t)e * 128;
                float* arow = g_agg + (size_t)sI0[r] * 128;
#pragma unroll
                for (int nt = 0; nt < 8; ++nt) {
                    int col = ncol0 + 8 * nt + tg * 2;
                    float2 resid = *(const float2*)(orow + col);
                    float o0 = resid.x + (acc[mt][nt][2 * p]     + b2v[nt].x - mu) * rs * gv[nt].x + bv[nt].x;
                    float o1 = resid.y + (acc[mt][nt][2 * p + 1] + b2v[nt].y - mu) * rs * gv[nt].y + bv[nt].y;
                    *(float2*)(orow + col) = make_float2(o0, o1);
                    asm volatile("red.global.add.v2.f32 [%0], {%1,%2};"
                                 :: "l"(arow + col), "f"(o0), "f"(o1) : "memory");
                }
            }
        }
}

// ---------------------------------------------------------------------------
// Fused node kernel: 128 nodes/block.
//   x_new = x + LN(relu(x@W1a + agg@W1b + b1)@W2 + b2)*g + beta
//   then (if matNA >= 0) P = x_new @ matNA, Q = x_new @ matNB for the NEXT layer.
//   Also zeroes its agg rows for the next layer (after consuming them).
__global__ void __launch_bounds__(256, 2)
node_kernel(float* __restrict__ xb, int matW1a, int matW1b, int matW2,
            const float* __restrict__ b1, const float* __restrict__ b2,
            const float* __restrict__ gln, const float* __restrict__ bln,
            int matNA, int matNB) {
    extern __shared__ char sm[];
    uint32_t sb = smem_u32(sm);
    int tid = threadIdx.x, w = tid >> 5, lane = tid & 31;
    int g = lane >> 2, tg = lane & 3;
    int base = blockIdx.x * 128;
    int mrow0 = (w >> 1) * 32, ncol0 = (w & 1) * 64;
    int nhalf = w & 1;

    copy_B_half(sb, matW1a, 0, tid);
    conv_tile(sm, xb, base, Nn - 1, tid);
    CP_WAIT0();
    __syncthreads();

    float acc[2][8][4];
    zero_acc(acc);
    gemm3(sm, sb, acc, matW1a, mrow0, ncol0, g, tg, tid);  // x @ nW1a
    __syncthreads();                            // A reads done -> safe to overwrite

    copy_B_half(sb, matW1b, 0, tid);
    conv_tile(sm, g_agg, base, Nn - 1, tid);
    // zero the agg rows this CTA owns (same thread->element map as conv reads)
#pragma unroll
    for (int ii = 0; ii < 16; ++ii) {
        int i = tid + ii * 256;
        int row = i >> 5, c = (i & 31) * 4;
        int gr = base + row;
        if (gr < Nn)
            *(float4*)(g_agg + (size_t)gr * 128 + c) = make_float4(0.f, 0.f, 0.f, 0.f);
    }
    CP_WAIT0();
    __syncthreads();
    gemm3(sm, sb, acc, matW1b, mrow0, ncol0, g, tg, tid);  // += agg @ nW1b
    __syncthreads();
    copy_B_half(sb, matW2, 0, tid);             // W2-hi fetch overlaps epi1

    // epi1: h = relu(D + b1) -> A tiles
    float2 b1v[8];
#pragma unroll
    for (int nt = 0; nt < 8; ++nt)
        b1v[nt] = *(const float2*)(b1 + ncol0 + 8 * nt + tg * 2);
#pragma unroll
    for (int mt = 0; mt < 2; ++mt)
#pragma unroll
        for (int p = 0; p < 2; ++p) {
            int r = mrow0 + 16 * mt + 8 * p + g;
#pragma unroll
            for (int nt = 0; nt < 8; ++nt) {
                int col = ncol0 + 8 * nt + tg * 2;
                float v0 = fmaxf(acc[mt][nt][2 * p]     + b1v[nt].x, 0.f);
                float v1 = fmaxf(acc[mt][nt][2 * p + 1] + b1v[nt].y, 0.f);
                uint32_t hi, lo;
                split2(v0, v1, hi, lo);
                int ob = r * ROWB + col * 2;
                *(uint32_t*)(sm + OFF_AHI + ob) = hi;
                *(uint32_t*)(sm + OFF_ALO + ob) = lo;
            }
        }
    CP_WAIT0();
    __syncthreads();

    zero_acc(acc);
    gemm3(sm, sb, acc, matW2, mrow0, ncol0, g, tg, tid);   // h @ nW2
    __syncthreads();                            // all A/B reads complete
    if (matNA >= 0) copy_B_half(sb, matNA, 0, tid);   // next layer eW1a-hi

    // epi2: x_new = x + LN(D + nb2)*g + beta ; write x, split x_new -> A tiles
    float2 b2v[8], gv[8], bv[8];
#pragma unroll
    for (int nt = 0; nt < 8; ++nt) {
        int col = ncol0 + 8 * nt + tg * 2;
        b2v[nt] = *(const float2*)(b2 + col);
        gv[nt]  = *(const float2*)(gln + col);
        bv[nt]  = *(const float2*)(bln + col);
    }
    float* sSum = (float*)(sm + OFF_RED);
    float* sSq  = (float*)(sm + OFF_RED + 1024);
#pragma unroll
    for (int mt = 0; mt < 2; ++mt)
#pragma unroll
        for (int p = 0; p < 2; ++p) {
            float s = 0.f, q = 0.f;
#pragma unroll
            for (int nt = 0; nt < 8; ++nt) {
                float v0 = acc[mt][nt][2 * p]     + b2v[nt].x;
                float v1 = acc[mt][nt][2 * p + 1] + b2v[nt].y;
                s += v0 + v1; q += v0 * v0 + v1 * v1;
            }
            s += __shfl_xor_sync(0xffffffff, s, 1); q += __shfl_xor_sync(0xffffffff, q, 1);
            s += __shfl_xor_sync(0xffffffff, s, 2); q += __shfl_xor_sync(0xffffffff, q, 2);
            int r = mrow0 + 16 * mt + 8 * p + g;
            if (tg == 0) { sSum[nhalf * 128 + r] = s; sSq[nhalf * 128 + r] = q; }
        }
    __syncthreads();
#pragma unroll
    for (int mt = 0; mt < 2; ++mt)
#pragma unroll
        for (int p = 0; p < 2; ++p) {
            int r = mrow0 + 16 * mt + 8 * p + g;
            float mu = (sSum[r] + sSum[128 + r]) * (1.f / 128.f);
            float qq = (sSq[r]  + sSq[128 + r])  * (1.f / 128.f);
            float rs = rsqrtf(qq - mu * mu + 1e-5f);
            int n = base + r;
            bool valid = n < Nn;
            const float* orow = xb + (size_t)(valid ? n : Nn - 1) * 128;
#pragma unroll
            for (int nt = 0; nt < 8; ++nt) {
                int col = ncol0 + 8 * nt + tg * 2;
                float2 resid = *(const float2*)(orow + col);
                float o0 = resid.x + (acc[mt][nt][2 * p]     + b2v[nt].x - mu) * rs * gv[nt].x + bv[nt].x;
                float o1 = resid.y + (acc[mt][nt][2 * p + 1] + b2v[nt].y - mu) * rs * gv[nt].y + bv[nt].y;
                if (valid)
                    *(float2*)((float*)(xb + (size_t)n * 128) + col) = make_float2(o0, o1);
                // split x_new into A tiles for the next-layer PQ gemms
                uint32_t hi, lo;
                split2(o0, o1, hi, lo);
                int ob = r * ROWB + col * 2;
                *(uint32_t*)(sm + OFF_AHI + ob) = hi;
                *(uint32_t*)(sm + OFF_ALO + ob) = lo;
            }
        }

    if (matNA < 0) return;   // last layer: no PQ for a next layer

    CP_WAIT0();
    __syncthreads();         // A tiles (x_new) + B (eW1a'-hi) ready

    zero_acc(acc);
    gemm3(sm, sb, acc, matNA, mrow0, ncol0, g, tg, tid);   // x_new @ eW1a'
    __syncthreads();
    copy_B_half(sb, matNB, 0, tid);             // eW1b'-hi overlaps P writeback

#pragma unroll
    for (int mt = 0; mt < 2; ++mt)
#pragma unroll
        for (int p = 0; p < 2; ++p) {
            int n = base + mrow0 + 16 * mt + 8 * p + g;
            if (n < Nn) {
                float* dst = g_PQ + (size_t)n * 256;
#pragma unroll
                for (int nt = 0; nt < 8; ++nt) {
                    int col = ncol0 + 8 * nt + tg * 2;
                    *(float2*)(dst + col) = make_float2(acc[mt][nt][2 * p], acc[mt][nt][2 * p + 1]);
                }
            }
        }
    CP_WAIT0();
    __syncthreads();
    zero_acc(acc);
    gemm3(sm, sb, acc, matNB, mrow0, ncol0, g, tg, tid);   // x_new @ eW1b'
#pragma unroll
    for (int mt = 0; mt < 2; ++mt)
#pragma unroll
        for (int p = 0; p < 2; ++p) {
            int n = base + mrow0 + 16 * mt + 8 * p + g;
            if (n < Nn) {
                float* dst = g_PQ + (size_t)n * 256 + 128;
#pragma unroll
                for (int nt = 0; nt < 8; ++nt) {
                    int col = ncol0 + 8 * nt + tg * 2;
                    *(float2*)(dst + col) = make_float2(acc[mt][nt][2 * p], acc[mt][nt][2 * p + 1]);
                }
            }
        }
}

// ---------------------------------------------------------------------------
extern "C" void kernel_launch(void* const* d_in, const int* in_sizes, int n_in,
                              void* d_out, int out_size) {
    const float* x   = (const float*)d_in[0];
    const int*   ei  = (const int*)  d_in[1];
    const float* ea  = (const float*)d_in[2];
    const float* eW1 = (const float*)d_in[3];
    const float* eb1 = (const float*)d_in[4];
    const float* eW2 = (const float*)d_in[5];
    const float* eb2 = (const float*)d_in[6];
    const float* eG  = (const float*)d_in[7];
    const float* eB  = (const float*)d_in[8];
    const float* nW1 = (const float*)d_in[9];
    const float* nb1 = (const float*)d_in[10];
    const float* nW2 = (const float*)d_in[11];
    const float* nb2 = (const float*)d_in[12];
    const float* nG  = (const float*)d_in[13];
    const float* nB  = (const float*)d_in[14];

    float* xb  = (float*)d_out;
    float* eab = xb + (size_t)Nn * 128;

    cudaFuncSetAttribute(pq_kernel,   cudaFuncAttributeMaxDynamicSharedMemorySize, SMEM_TOTAL);
    cudaFuncSetAttribute(edge_kernel, cudaFuncAttributeMaxDynamicSharedMemorySize, SMEM_TOTAL);
    cudaFuncSetAttribute(node_kernel, cudaFuncAttributeMaxDynamicSharedMemorySize, SMEM_TOTAL);

    cudaMemcpyAsync(xb,  x,  sizeof(float) * (size_t)Nn * 128, cudaMemcpyDeviceToDevice);
    cudaMemcpyAsync(eab, ea, sizeof(float) * (size_t)Ee * 128, cudaMemcpyDeviceToDevice);

    prep_w<<<28, 256>>>(eW1, eW2, nW1, nW2);
    zero_agg_kernel<<<(Nn * 128 / 4 + 255) / 256, 256>>>();

    const int nGrid = (Nn + 127) / 128;   // 391
    const int eGrid = (Ee + 127) / 128;   // 1954

    pq_kernel<<<nGrid, 256, SMEM_TOTAL>>>(xb, 0, 1);   // layer-0 P,Q

    for (int l = 0; l < Ll; ++l) {
        int m = l * 7;
        edge_kernel<<<eGrid, 256, SMEM_TOTAL>>>(eab, ei, m + 2, m + 3,
                                                eb1 + l * 128, eb2 + l * 128,
                                                eG + l * 128, eB + l * 128);
        int nxtA = (l < Ll - 1) ? (l + 1) * 7 + 0 : -1;
        int nxtB = (l < Ll - 1) ? (l + 1) * 7 + 1 : -1;
        node_kernel<<<nGrid, 256, SMEM_TOTAL>>>(xb, m + 4, m + 5, m + 6,
                                                nb1 + l * 128, nb2 + l * 128,
                                                nG + l * 128, nB + l * 128,
                                                nxtA, nxtB);
    }
}

// round 17
// speedup vs baseline: 1.1412x; 1.1412x over previous
#include <cuda_runtime.h>
#include <cuda_bf16.h>
#include <cstdint>
#include <cstddef>

#define Nn 50000
#define Ee 250000
#define Ll 4

// bf16 tile layout: [rows][136 cols] bf16 (row pad 8 -> 272B stride, conflict-free)
// M-tile = 64 rows everywhere.
// EDGE kernel:  A hi/lo (2x17408) + single B buffer (34816)  -> 70.7KB, 3 CTA/SM
// NODE/PQ:      A hi/lo (2x17408) + double B hi+lo (69632)   -> 104.4KB, 2 CTA/SM
#define ROWB 272
#define OFF_AHI 0u
#define OFF_ALO 17408u
// edge layout
#define E_OFF_B   34816u
#define E_OFF_RED 69632u
#define SMEM_EDGE (69632 + 1024)
// node layout
#define N_BHI     34816u
#define N_BLO     69632u
#define N_OFF_RED 104448u
#define SMEM_NODE (104448 + 1024)

// ---------------- global scratch (static, allocation-free) ----------------
__device__ float g_PQ[(size_t)Nn * 256];                 // [N][256]: P | Q
__device__ float g_agg[(size_t)Nn * 128];                // scatter accumulator
__device__ __align__(16) unsigned char g_Wb[28 * 69632]; // prepped weights (hi + lo tiles)

// ---------------------------------------------------------------------------
__device__ __forceinline__ uint32_t smem_u32(const void* p) {
    uint32_t a;
    asm("{ .reg .u64 t; cvta.to.shared.u64 t, %1; cvt.u32.u64 %0, t; }" : "=r"(a) : "l"(p));
    return a;
}

__device__ __forceinline__ void split2(float x, float y, uint32_t& hi, uint32_t& lo) {
    __nv_bfloat162 h = __floats2bfloat162_rn(x, y);
    float2 hf = __bfloat1622float2(h);
    __nv_bfloat162 l = __floats2bfloat162_rn(x - hf.x, y - hf.y);
    hi = *reinterpret_cast<uint32_t*>(&h);
    lo = *reinterpret_cast<uint32_t*>(&l);
}

__device__ __forceinline__ void mma_bf16(float* d, uint32_t a0, uint32_t a1, uint32_t a2,
                                         uint32_t a3, uint32_t b0, uint32_t b1) {
    asm volatile(
        "mma.sync.aligned.m16n8k16.row.col.f32.bf16.bf16.f32 "
        "{%0,%1,%2,%3}, {%4,%5,%6,%7}, {%8,%9}, {%0,%1,%2,%3};"
        : "+f"(d[0]), "+f"(d[1]), "+f"(d[2]), "+f"(d[3])
        : "r"(a0), "r"(a1), "r"(a2), "r"(a3), "r"(b0), "r"(b1));
}

#define CP_WAIT0() asm volatile("cp.async.wait_group 0;" ::: "memory")

__device__ __forceinline__ void zero_acc(float (&acc)[8][4]) {
#pragma unroll
    for (int b = 0; b < 8; ++b)
#pragma unroll
        for (int c = 0; c < 4; ++c) acc[b][c] = 0.f;
}

// convert a [64 x 128] fp32 slab (rows clamped) into hi/lo padded bf16 tiles
__device__ __forceinline__ void conv_tile(char* sm, const float* __restrict__ src,
                                          int base, int maxrow, int tid) {
#pragma unroll
    for (int ii = 0; ii < 8; ++ii) {
        int i = tid + ii * 256;
        int row = i >> 5, c = (i & 31) * 4;
        int gr = base + row; if (gr > maxrow) gr = maxrow;
        float4 v = *(const float4*)(src + (size_t)gr * 128 + c);
        uint32_t h0, l0, h1, l1;
        split2(v.x, v.y, h0, l0);
        split2(v.z, v.w, h1, l1);
        int ob = row * ROWB + c * 2;
        *(uint2*)(sm + OFF_AHI + ob) = make_uint2(h0, h1);
        *(uint2*)(sm + OFF_ALO + ob) = make_uint2(l0, l1);
    }
}

// -------- EDGE-side GEMM: single-B two-pass (r11-proven) --------
template <int TWO_TERM>
__device__ __forceinline__ void gemm_pass(const char* sm, float (&acc)[8][4],
                                          int mrow0, int ncol0, int g, int tg) {
    const char* Ah = sm + OFF_AHI;
    const char* Al = sm + OFF_ALO;
    const char* Bp = sm + E_OFF_B;
#pragma unroll
    for (int ks = 0; ks < 8; ++ks) {
        int kb = ks * 32 + tg * 4;
        int r = mrow0 + g;
        const char* p0 = Ah + r * ROWB + kb;
        const char* p1 = Ah + (r + 8) * ROWB + kb;
        uint32_t aH0 = *(const uint32_t*)(p0);
        uint32_t aH1 = *(const uint32_t*)(p1);
        uint32_t aH2 = *(const uint32_t*)(p0 + 16);
        uint32_t aH3 = *(const uint32_t*)(p1 + 16);
        uint32_t aL0 = 0, aL1 = 0, aL2 = 0, aL3 = 0;
        if (TWO_TERM) {
            const char* q0 = Al + r * ROWB + kb;
            const char* q1 = Al + (r + 8) * ROWB + kb;
            aL0 = *(const uint32_t*)(q0);
            aL1 = *(const uint32_t*)(q1);
            aL2 = *(const uint32_t*)(q0 + 16);
            aL3 = *(const uint32_t*)(q1 + 16);
        }
#pragma unroll
        for (int nh = 0; nh < 2; ++nh) {
            uint32_t bF[4][2];
#pragma unroll
            for (int ntl = 0; ntl < 4; ++ntl) {
                int n = ncol0 + 8 * (nh * 4 + ntl) + g;
                const char* p = Bp + n * ROWB + kb;
                bF[ntl][0] = *(const uint32_t*)(p);
                bF[ntl][1] = *(const uint32_t*)(p + 16);
            }
#pragma unroll
            for (int ntl = 0; ntl < 4; ++ntl) {
                float* d = acc[nh * 4 + ntl];
                mma_bf16(d, aH0, aH1, aH2, aH3, bF[ntl][0], bF[ntl][1]);
                if (TWO_TERM)
                    mma_bf16(d, aL0, aL1, aL2, aL3, bF[ntl][0], bF[ntl][1]);
            }
        }
    }
}

// async copy one half (hi=0 / lo=1) of a weight record (34816B) to edge B buffer
__device__ __forceinline__ void copy_B_half(uint32_t sb, int mat, int half, int tid) {
    const char* s = (const char*)(g_Wb + (size_t)mat * 69632 + (size_t)half * 34816);
    uint32_t d = sb + E_OFF_B;
#pragma unroll
    for (int ii = 0; ii < 9; ++ii) {
        int i = tid + ii * 256;
        if (i < 2176)
            asm volatile("cp.async.cg.shared.global [%0], [%1], 16;"
                         :: "r"(d + i * 16), "l"(s + (size_t)i * 16) : "memory");
    }
    asm volatile("cp.async.commit_group;" ::: "memory");
}

// full 3-term GEMM via two passes over the single B buffer (edge)
__device__ __forceinline__ void gemm3(const char* sm, uint32_t sb, float (&acc)[8][4],
                                      int mat, int mrow0, int ncol0, int g, int tg, int tid) {
    gemm_pass<1>(sm, acc, mrow0, ncol0, g, tg);
    __syncthreads();
    copy_B_half(sb, mat, 1, tid);
    CP_WAIT0();
    __syncthreads();
    gemm_pass<0>(sm, acc, mrow0, ncol0, g, tg);
}

// -------- NODE-side GEMM: double-B one-pass (r6-proven) --------
__device__ __forceinline__ void gemm_full(const char* sm, float (&acc)[8][4],
                                          int mrow0, int ncol0, int g, int tg) {
    const char* Ah = sm + OFF_AHI;
    const char* Al = sm + OFF_ALO;
    const char* Bh = sm + N_BHI;
    const char* Bl = sm + N_BLO;
#pragma unroll
    for (int ks = 0; ks < 8; ++ks) {
        int kb = ks * 32 + tg * 4;
        int r = mrow0 + g;
        const char* p0 = Ah + r * ROWB + kb;
        const char* p1 = Ah + (r + 8) * ROWB + kb;
        uint32_t aH0 = *(const uint32_t*)(p0);
        uint32_t aH1 = *(const uint32_t*)(p1);
        uint32_t aH2 = *(const uint32_t*)(p0 + 16);
        uint32_t aH3 = *(const uint32_t*)(p1 + 16);
        const char* q0 = Al + r * ROWB + kb;
        const char* q1 = Al + (r + 8) * ROWB + kb;
        uint32_t aL0 = *(const uint32_t*)(q0);
        uint32_t aL1 = *(const uint32_t*)(q1);
        uint32_t aL2 = *(const uint32_t*)(q0 + 16);
        uint32_t aL3 = *(const uint32_t*)(q1 + 16);
#pragma unroll
        for (int nh = 0; nh < 2; ++nh) {
            uint32_t bH[4][2], bL[4][2];
#pragma unroll
            for (int ntl = 0; ntl < 4; ++ntl) {
                int n = ncol0 + 8 * (nh * 4 + ntl) + g;
                const char* p = Bh + n * ROWB + kb;
                bH[ntl][0] = *(const uint32_t*)(p);
                bH[ntl][1] = *(const uint32_t*)(p + 16);
                const char* q = Bl + n * ROWB + kb;
                bL[ntl][0] = *(const uint32_t*)(q);
                bL[ntl][1] = *(const uint32_t*)(q + 16);
            }
#pragma unroll
            for (int ntl = 0; ntl < 4; ++ntl) {
                float* d = acc[nh * 4 + ntl];
                mma_bf16(d, aH0, aH1, aH2, aH3, bH[ntl][0], bH[ntl][1]);
                mma_bf16(d, aH0, aH1, aH2, aH3, bL[ntl][0], bL[ntl][1]);
                mma_bf16(d, aL0, aL1, aL2, aL3, bH[ntl][0], bH[ntl][1]);
            }
        }
    }
}

// async copy a full weight record (hi+lo, 69632B) to node B region
__device__ __forceinline__ void copy_B_full(uint32_t sb, int mat, int tid) {
    const char* s = (const char*)(g_Wb + (size_t)mat * 69632);
    uint32_t d = sb + N_BHI;
#pragma unroll
    for (int ii = 0; ii < 17; ++ii) {
        int i = tid + ii * 256;
        asm volatile("cp.async.cg.shared.global [%0], [%1], 16;"
                     :: "r"(d + i * 16), "l"(s + (size_t)i * 16) : "memory");
    }
    asm volatile("cp.async.commit_group;" ::: "memory");
}

// ---------------------------------------------------------------------------
__global__ void zero_agg_kernel() {
    int i = blockIdx.x * blockDim.x + threadIdx.x;
    if (i < (Nn * 128) / 4) {
        float4 z = {0.f, 0.f, 0.f, 0.f};
        ((float4*)g_agg)[i] = z;
    }
}

// Pre-transpose + split into padded bf16 [n][k] layout. 28 matrices.
__global__ void prep_w(const float* __restrict__ eW1, const float* __restrict__ eW2,
                       const float* __restrict__ nW1, const float* __restrict__ nW2) {
    int m = blockIdx.x, l = m / 7, t = m % 7;
    const float* W;
    switch (t) {
        case 0: W = eW1 + (size_t)l * 3 * 16384;          break;
        case 1: W = eW1 + (size_t)l * 3 * 16384 + 16384;  break;
        case 2: W = eW1 + (size_t)l * 3 * 16384 + 32768;  break;
        case 3: W = eW2 + (size_t)l * 16384;              break;
        case 4: W = nW1 + (size_t)l * 2 * 16384;          break;
        case 5: W = nW1 + (size_t)l * 2 * 16384 + 16384;  break;
        default: W = nW2 + (size_t)l * 16384;             break;
    }
    size_t rec = (size_t)m * 69632;
    for (int i = threadIdx.x; i < 2048; i += 256) {
        int n = i >> 4, k8 = (i & 15) * 8;
        uint32_t hi[4], lo[4];
#pragma unroll
        for (int gi = 0; gi < 4; ++gi) {
            float a = W[(size_t)(k8 + 2 * gi) * 128 + n];
            float b = W[(size_t)(k8 + 2 * gi + 1) * 128 + n];
            split2(a, b, hi[gi], lo[gi]);
        }
        size_t ob = rec + (size_t)n * ROWB + k8 * 2;
        *(uint4*)(g_Wb + ob)         = make_uint4(hi[0], hi[1], hi[2], hi[3]);
        *(uint4*)(g_Wb + ob + 34816) = make_uint4(lo[0], lo[1], lo[2], lo[3]);
    }
}

// ---------------------------------------------------------------------------
// PQ = x @ [W1a | W1b] -> g_PQ.  64 nodes/block.  (layer 0 only; reads x input)
__global__ void __launch_bounds__(256, 2)
pq_kernel(const float* __restrict__ xs, int matA, int matB) {
    extern __shared__ char sm[];
    uint32_t sb = smem_u32(sm);
    int tid = threadIdx.x, w = tid >> 5, lane = tid & 31;
    int g = lane >> 2, tg = lane & 3;
    int base = blockIdx.x * 64;
    int mrow0 = (w >> 1) * 16, ncol0 = (w & 1) * 64;

    copy_B_full(sb, matA, tid);
    conv_tile(sm, xs, base, Nn - 1, tid);
    CP_WAIT0();
    __syncthreads();

    float acc[8][4];
    zero_acc(acc);
    gemm_full(sm, acc, mrow0, ncol0, g, tg);
    __syncthreads();
    copy_B_full(sb, matB, tid);      // W1b fetch overlaps P writeback

#pragma unroll
    for (int p = 0; p < 2; ++p) {
        int n = base + mrow0 + 8 * p + g;
        if (n < Nn) {
            float* dst = g_PQ + (size_t)n * 256;
#pragma unroll
            for (int nt = 0; nt < 8; ++nt) {
                int col = ncol0 + 8 * nt + tg * 2;
                *(float2*)(dst + col) = make_float2(acc[nt][2 * p], acc[nt][2 * p + 1]);
            }
        }
    }
    CP_WAIT0();
    __syncthreads();
    zero_acc(acc);
    gemm_full(sm, acc, mrow0, ncol0, g, tg);
#pragma unroll
    for (int p = 0; p < 2; ++p) {
        int n = base + mrow0 + 8 * p + g;
        if (n < Nn) {
            float* dst = g_PQ + (size_t)n * 256 + 128;
#pragma unroll
            for (int nt = 0; nt < 8; ++nt) {
                int col = ncol0 + 8 * nt + tg * 2;
                *(float2*)(dst + col) = make_float2(acc[nt][2 * p], acc[nt][2 * p + 1]);
            }
        }
    }
}

// ---------------------------------------------------------------------------
// Fused edge kernel: 64 edges/block. Single-B two-pass, 3 CTA/SM (r11-proven).
// src = edge-attr source (layer0: original input), dst = eab output.
__global__ void __launch_bounds__(256, 3)
edge_kernel(const float* __restrict__ src, float* __restrict__ dst,
            const int* __restrict__ ei, int matW1c, int matW2,
            const float* __restrict__ b1, const float* __restrict__ b2,
            const float* __restrict__ gln, const float* __restrict__ bln) {
    extern __shared__ char sm[];
    uint32_t sb = smem_u32(sm);
    __shared__ int sI0[64], sI1[64];
    int tid = threadIdx.x, w = tid >> 5, lane = tid & 31;
    int g = lane >> 2, tg = lane & 3;
    int base = blockIdx.x * 64;
    int mrow0 = (w >> 1) * 16, ncol0 = (w & 1) * 64;
    int nhalf = w & 1;

    if (tid < 64) {
        int e = base + tid; if (e > Ee - 1) e = Ee - 1;
        sI0[tid] = ei[e];
        sI1[tid] = ei[Ee + e];
    }
    copy_B_half(sb, matW1c, 0, tid);
    conv_tile(sm, src, base, Ee - 1, tid);
    CP_WAIT0();
    __syncthreads();

    float acc[8][4];
    zero_acc(acc);
    gemm3(sm, sb, acc, matW1c, mrow0, ncol0, g, tg, tid);   // ea @ W1c
    __syncthreads();                            // all A/B reads complete
    copy_B_half(sb, matW2, 0, tid);             // W2-hi fetch overlaps epi1 gathers

    // epi1: h = relu(D + P[i1] + Q[i0] + b1) -> back into A tiles (hi/lo)
    float2 b1v[8];
#pragma unroll
    for (int nt = 0; nt < 8; ++nt)
        b1v[nt] = *(const float2*)(b1 + ncol0 + 8 * nt + tg * 2);
#pragma unroll
    for (int p = 0; p < 2; ++p) {
        int r = mrow0 + 8 * p + g;
        const float* Pp = g_PQ + (size_t)sI1[r] * 256;
        const float* Qp = g_PQ + (size_t)sI0[r] * 256 + 128;
#pragma unroll
        for (int nt = 0; nt < 8; ++nt) {
            int col = ncol0 + 8 * nt + tg * 2;
            float2 pv = *(const float2*)(Pp + col);
            float2 qv = *(const float2*)(Qp + col);
            float v0 = fmaxf(acc[nt][2 * p]     + pv.x + qv.x + b1v[nt].x, 0.f);
            float v1 = fmaxf(acc[nt][2 * p + 1] + pv.y + qv.y + b1v[nt].y, 0.f);
            uint32_t hi, lo;
            split2(v0, v1, hi, lo);
            int ob = r * ROWB + col * 2;
            *(uint32_t*)(sm + OFF_AHI + ob) = hi;
            *(uint32_t*)(sm + OFF_ALO + ob) = lo;
        }
    }
    CP_WAIT0();
    __syncthreads();

    zero_acc(acc);
    gemm3(sm, sb, acc, matW2, mrow0, ncol0, g, tg, tid);   // h @ W2

    // epi2: LN + residual + scatter
    float2 b2v[8], gv[8], bv[8];
#pragma unroll
    for (int nt = 0; nt < 8; ++nt) {
        int col = ncol0 + 8 * nt + tg * 2;
        b2v[nt] = *(const float2*)(b2 + col);
        gv[nt]  = *(const float2*)(gln + col);
        bv[nt]  = *(const float2*)(bln + col);
    }
    float* sSum = (float*)(sm + E_OFF_RED);
    float* sSq  = (float*)(sm + E_OFF_RED + 512);
#pragma unroll
    for (int p = 0; p < 2; ++p) {
        float s = 0.f, q = 0.f;
#pragma unroll
        for (int nt = 0; nt < 8; ++nt) {
            float v0 = acc[nt][2 * p]     + b2v[nt].x;
            float v1 = acc[nt][2 * p + 1] + b2v[nt].y;
            s += v0 + v1; q += v0 * v0 + v1 * v1;
        }
        s += __shfl_xor_sync(0xffffffff, s, 1); q += __shfl_xor_sync(0xffffffff, q, 1);
        s += __shfl_xor_sync(0xffffffff, s, 2); q += __shfl_xor_sync(0xffffffff, q, 2);
        int r = mrow0 + 8 * p + g;
        if (tg == 0) { sSum[nhalf * 64 + r] = s; sSq[nhalf * 64 + r] = q; }
    }
    __syncthreads();
#pragma unroll
    for (int p = 0; p < 2; ++p) {
        int r = mrow0 + 8 * p + g;
        float mu = (sSum[r] + sSum[64 + r]) * (1.f / 128.f);
        float qq = (sSq[r]  + sSq[64 + r])  * (1.f / 128.f);
        float rs = rsqrtf(qq - mu * mu + 1e-5f);
        int e = base + r;
        if (e < Ee) {
            const float* irow = src + (size_t)e * 128;
            float* orow = dst + (size_t)e * 128;
            float* arow = g_agg + (size_t)sI0[r] * 128;
#pragma unroll
            for (int nt = 0; nt < 8; ++nt) {
                int col = ncol0 + 8 * nt + tg * 2;
                float2 resid = *(const float2*)(irow + col);
                float o0 = resid.x + (acc[nt][2 * p]     + b2v[nt].x - mu) * rs * gv[nt].x + bv[nt].x;
                float o1 = resid.y + (acc[nt][2 * p + 1] + b2v[nt].y - mu) * rs * gv[nt].y + bv[nt].y;
                *(float2*)(orow + col) = make_float2(o0, o1);
                asm volatile("red.global.add.v2.f32 [%0], {%1,%2};"
                             :: "l"(arow + col), "f"(o0), "f"(o1) : "memory");
            }
        }
    }
}

// ---------------------------------------------------------------------------
// Fused node kernel: 64 nodes/block. Double-B one-pass, 2 CTA/SM (r6-proven).
//   x_new = xs + LN(relu(xs@W1a + agg@W1b + b1)@W2 + b2)*g + beta -> xb
//   then (if matNA >= 0) P = x_new @ matNA, Q = x_new @ matNB for the NEXT layer.
//   Also zeroes its agg rows for the next layer (after consuming them).
__global__ void __launch_bounds__(256, 2)
node_kernel(const float* __restrict__ xs, float* __restrict__ xb,
            int matW1a, int matW1b, int matW2,
            const float* __restrict__ b1, const float* __restrict__ b2,
            const float* __restrict__ gln, const float* __restrict__ bln,
            int matNA, int matNB) {
    extern __shared__ char sm[];
    uint32_t sb = smem_u32(sm);
    int tid = threadIdx.x, w = tid >> 5, lane = tid & 31;
    int g = lane >> 2, tg = lane & 3;
    int base = blockIdx.x * 64;
    int mrow0 = (w >> 1) * 16, ncol0 = (w & 1) * 64;
    int nhalf = w & 1;

    copy_B_full(sb, matW1a, tid);
    conv_tile(sm, xs, base, Nn - 1, tid);
    CP_WAIT0();
    __syncthreads();

    float acc[8][4];
    zero_acc(acc);
    gemm_full(sm, acc, mrow0, ncol0, g, tg);   // x @ nW1a
    __syncthreads();

    copy_B_full(sb, matW1b, tid);
    conv_tile(sm, g_agg, base, Nn - 1, tid);
    // zero the agg rows this CTA owns (ready for next layer's edge scatter)
#pragma unroll
    for (int ii = 0; ii < 8; ++ii) {
        int i = tid + ii * 256;
        int row = i >> 5, c = (i & 31) * 4;
        int gr = base + row;
        if (gr < Nn)
            *(float4*)(g_agg + (size_t)gr * 128 + c) = make_float4(0.f, 0.f, 0.f, 0.f);
    }
    CP_WAIT0();
    __syncthreads();
    gemm_full(sm, acc, mrow0, ncol0, g, tg);   // += agg @ nW1b
    __syncthreads();
    copy_B_full(sb, matW2, tid);               // W2 fetch overlaps epi1

    // epi1: h = relu(D + b1) -> A tiles
    float2 b1v[8];
#pragma unroll
    for (int nt = 0; nt < 8; ++nt)
        b1v[nt] = *(const float2*)(b1 + ncol0 + 8 * nt + tg * 2);
#pragma unroll
    for (int p = 0; p < 2; ++p) {
        int r = mrow0 + 8 * p + g;
#pragma unroll
        for (int nt = 0; nt < 8; ++nt) {
            int col = ncol0 + 8 * nt + tg * 2;
            float v0 = fmaxf(acc[nt][2 * p]     + b1v[nt].x, 0.f);
            float v1 = fmaxf(acc[nt][2 * p + 1] + b1v[nt].y, 0.f);
            uint32_t hi, lo;
            split2(v0, v1, hi, lo);
            int ob = r * ROWB + col * 2;
            *(uint32_t*)(sm + OFF_AHI + ob) = hi;
            *(uint32_t*)(sm + OFF_ALO + ob) = lo;
        }
    }
    CP_WAIT0();
    __syncthreads();

    zero_acc(acc);
    gemm_full(sm, acc, mrow0, ncol0, g, tg);   // h @ nW2
    __syncthreads();                            // all A/B reads complete
    if (matNA >= 0) copy_B_full(sb, matNA, tid);   // next layer eW1a

    // epi2: x_new = xs + LN(D + nb2)*g + beta ; write xb, split x_new -> A tiles
    float2 b2v[8], gv[8], bv[8];
#pragma unroll
    for (int nt = 0; nt < 8; ++nt) {
        int col = ncol0 + 8 * nt + tg * 2;
        b2v[nt] = *(const float2*)(b2 + col);
        gv[nt]  = *(const float2*)(gln + col);
        bv[nt]  = *(const float2*)(bln + col);
    }
    float* sSum = (float*)(sm + N_OFF_RED);
    float* sSq  = (float*)(sm + N_OFF_RED + 512);
#pragma unroll
    for (int p = 0; p < 2; ++p) {
        float s = 0.f, q = 0.f;
#pragma unroll
        for (int nt = 0; nt < 8; ++nt) {
            float v0 = acc[nt][2 * p]     + b2v[nt].x;
            float v1 = acc[nt][2 * p + 1] + b2v[nt].y;
            s += v0 + v1; q += v0 * v0 + v1 * v1;
        }
        s += __shfl_xor_sync(0xffffffff, s, 1); q += __shfl_xor_sync(0xffffffff, q, 1);
        s += __shfl_xor_sync(0xffffffff, s, 2); q += __shfl_xor_sync(0xffffffff, q, 2);
        int r = mrow0 + 8 * p + g;
        if (tg == 0) { sSum[nhalf * 64 + r] = s; sSq[nhalf * 64 + r] = q; }
    }
    __syncthreads();
#pragma unroll
    for (int p = 0; p < 2; ++p) {
        int r = mrow0 + 8 * p + g;
        float mu = (sSum[r] + sSum[64 + r]) * (1.f / 128.f);
        float qq = (sSq[r]  + sSq[64 + r])  * (1.f / 128.f);
        float rs = rsqrtf(qq - mu * mu + 1e-5f);
        int n = base + r;
        bool valid = n < Nn;
        const float* irow = xs + (size_t)(valid ? n : Nn - 1) * 128;
#pragma unroll
        for (int nt = 0; nt < 8; ++nt) {
            int col = ncol0 + 8 * nt + tg * 2;
            float2 resid = *(const float2*)(irow + col);
            float o0 = resid.x + (acc[nt][2 * p]     + b2v[nt].x - mu) * rs * gv[nt].x + bv[nt].x;
            float o1 = resid.y + (acc[nt][2 * p + 1] + b2v[nt].y - mu) * rs * gv[nt].y + bv[nt].y;
            if (valid)
                *(float2*)(xb + (size_t)n * 128 + col) = make_float2(o0, o1);
            // split x_new into A tiles for the next-layer PQ gemms
            uint32_t hi, lo;
            split2(o0, o1, hi, lo);
            int ob = r * ROWB + col * 2;
            *(uint32_t*)(sm + OFF_AHI + ob) = hi;
            *(uint32_t*)(sm + OFF_ALO + ob) = lo;
        }
    }

    if (matNA < 0) return;   // last layer: no PQ for a next layer

    CP_WAIT0();
    __syncthreads();         // A tiles (x_new) + B (eW1a') ready

    zero_acc(acc);
    gemm_full(sm, acc, mrow0, ncol0, g, tg);   // x_new @ eW1a'
    __syncthreads();
    copy_B_full(sb, matNB, tid);               // eW1b' overlaps P writeback

#pragma unroll
    for (int p = 0; p < 2; ++p) {
        int n = base + mrow0 + 8 * p + g;
        if (n < Nn) {
            float* dst = g_PQ + (size_t)n * 256;
#pragma unroll
            for (int nt = 0; nt < 8; ++nt) {
                int col = ncol0 + 8 * nt + tg * 2;
                *(float2*)(dst + col) = make_float2(acc[nt][2 * p], acc[nt][2 * p + 1]);
            }
        }
    }
    CP_WAIT0();
    __syncthreads();
    zero_acc(acc);
    gemm_full(sm, acc, mrow0, ncol0, g, tg);   // x_new @ eW1b'
#pragma unroll
    for (int p = 0; p < 2; ++p) {
        int n = base + mrow0 + 8 * p + g;
        if (n < Nn) {
            float* dst = g_PQ + (size_t)n * 256 + 128;
#pragma unroll
            for (int nt = 0; nt < 8; ++nt) {
                int col = ncol0 + 8 * nt + tg * 2;
                *(float2*)(dst + col) = make_float2(acc[nt][2 * p], acc[nt][2 * p + 1]);
            }
        }
    }
}

// ---------------------------------------------------------------------------
extern "C" void kernel_launch(void* const* d_in, const int* in_sizes, int n_in,
                              void* d_out, int out_size) {
    const float* x   = (const float*)d_in[0];
    const int*   ei  = (const int*)  d_in[1];
    const float* ea  = (const float*)d_in[2];
    const float* eW1 = (const float*)d_in[3];
    const float* eb1 = (const float*)d_in[4];
    const float* eW2 = (const float*)d_in[5];
    const float* eb2 = (const float*)d_in[6];
    const float* eG  = (const float*)d_in[7];
    const float* eB  = (const float*)d_in[8];
    const float* nW1 = (const float*)d_in[9];
    const float* nb1 = (const float*)d_in[10];
    const float* nW2 = (const float*)d_in[11];
    const float* nb2 = (const float*)d_in[12];
    const float* nG  = (const float*)d_in[13];
    const float* nB  = (const float*)d_in[14];

    float* xb  = (float*)d_out;
    float* eab = xb + (size_t)Nn * 128;

    cudaFuncSetAttribute(pq_kernel,   cudaFuncAttributeMaxDynamicSharedMemorySize, SMEM_NODE);
    cudaFuncSetAttribute(edge_kernel, cudaFuncAttributeMaxDynamicSharedMemorySize, SMEM_EDGE);
    cudaFuncSetAttribute(node_kernel, cudaFuncAttributeMaxDynamicSharedMemorySize, SMEM_NODE);

    prep_w<<<28, 256>>>(eW1, eW2, nW1, nW2);
    zero_agg_kernel<<<(Nn * 128 / 4 + 255) / 256, 256>>>();

    const int nGrid = (Nn + 63) / 64;   // 782
    const int eGrid = (Ee + 63) / 64;   // 3907

    pq_kernel<<<nGrid, 256, SMEM_NODE>>>(x, 0, 1);   // layer-0 P,Q from input x

    for (int l = 0; l < Ll; ++l) {
        int m = l * 7;
        const float* eaSrc = (l == 0) ? ea : eab;
        const float* xSrc  = (l == 0) ? x  : xb;
        edge_kernel<<<eGrid, 256, SMEM_EDGE>>>(eaSrc, eab, ei, m + 2, m + 3,
                                               eb1 + l * 128, eb2 + l * 128,
                                               eG + l * 128, eB + l * 128);
        int nxtA = (l < Ll - 1) ? (l + 1) * 7 + 0 : -1;
        int nxtB = (l < Ll - 1) ? (l + 1) * 7 + 1 : -1;
        node_kernel<<<nGrid, 256, SMEM_NODE>>>(xSrc, xb, m + 4, m + 5, m + 6,
                                               nb1 + l * 128, nb2 + l * 128,
                                               nG + l * 128, nB + l * 128,
                                               nxtA, nxtB);
    }
}